// round 7
// baseline (speedup 1.0000x reference)
#include <cuda_runtime.h>
#include <cuda_bf16.h>
#include <math.h>

// Problem constants (fixed by the dataset)
#define NN    50000     // nodes
#define EE    800000    // edges
#define C_IN  128
#define C_HID 256
#define C_OUT 64

// ---------------- scratch (device globals; no allocation, no host API) -----
__device__ int   g_is64;            // 1 if edge_index delivered as int64
__device__ int   g_row[EE];
__device__ int   g_col[EE];
__device__ int   g_deg[NN];
__device__ float g_dinv[NN];
__device__ int   g_off[NN + 1];
__device__ int   g_cursor[NN];
__device__ int   g_csr[EE];
__device__ float g_bufA[(size_t)NN * C_HID];   // features (layer input)
__device__ float g_bufB[(size_t)NN * C_HID];   // x_lin (GEMM output)

// ---------------- dtype sniffer ---------------------------------------------
// If the buffer holds int64 values < 2^31, every odd int32 word is 0.
// For genuine int32 node ids (random in [0, 50000)), that's impossible.
__global__ void k_detect(const int* __restrict__ ei32) {
    int all_zero = 1;
    #pragma unroll
    for (int i = 0; i < 64; i++)
        if (ei32[2 * i + 1] != 0) all_zero = 0;
    g_is64 = all_zero;
}

// ---------------- small prep kernels ---------------------------------------
__global__ void k_zero_deg(int n) {
    int i = blockIdx.x * blockDim.x + threadIdx.x;
    if (i < n) g_deg[i] = 0;
}

__global__ void k_prep_edges(const void* __restrict__ ei, int e) {
    int idx = blockIdx.x * blockDim.x + threadIdx.x;
    if (idx >= e) return;
    int r, c;
    if (g_is64) {
        const long long* p = (const long long*)ei;
        r = (int)p[idx];
        c = (int)p[(size_t)e + idx];
    } else {
        const int* p = (const int*)ei;
        r = p[idx];
        c = p[(size_t)e + idx];
    }
    g_row[idx] = r;
    g_col[idx] = c;
    atomicAdd(&g_deg[c], 1);
}

__global__ void k_dinv(int n) {
    int i = blockIdx.x * blockDim.x + threadIdx.x;
    if (i < n) g_dinv[i] = rsqrtf((float)(g_deg[i] + 1));
}

// single-block exclusive scan of g_deg -> g_off (and g_cursor copy)
__global__ void k_scan(int n) {
    __shared__ int buf[1024];
    __shared__ int carry;
    int tid = threadIdx.x;
    if (tid == 0) carry = 0;
    __syncthreads();
    for (int base = 0; base < n; base += 1024) {
        int v = (base + tid < n) ? g_deg[base + tid] : 0;
        buf[tid] = v;
        __syncthreads();
        #pragma unroll
        for (int s = 1; s < 1024; s <<= 1) {
            int t = (tid >= s) ? buf[tid - s] : 0;
            __syncthreads();
            buf[tid] += t;
            __syncthreads();
        }
        int excl = carry + buf[tid] - v;
        if (base + tid < n) { g_off[base + tid] = excl; g_cursor[base + tid] = excl; }
        __syncthreads();
        if (tid == 1023) carry += buf[1023];
        __syncthreads();
    }
    if (tid == 0) g_off[n] = carry;
}

__global__ void k_fill_csr(int e) {
    int idx = blockIdx.x * blockDim.x + threadIdx.x;
    if (idx >= e) return;
    int c = g_col[idx];
    int p = atomicAdd(&g_cursor[c], 1);
    g_csr[p] = g_row[idx];
}

// ---------------- SGEMM: g_bufB[N,M] = A[N,K] @ B[K,M] ----------------------
// A_EXT selects external pointer vs. g_bufA scratch (no host symbol lookups).
template <int BM, int BN, int BK, int TM, int TN, bool A_EXT>
__global__ __launch_bounds__((BM / TM) * (BN / TN))
void k_sgemm(const float* __restrict__ Aext, const float* __restrict__ B,
             int N, int K, int M) {
    const float* __restrict__ A = A_EXT ? Aext : (const float*)g_bufA;
    float* __restrict__ C = g_bufB;

    constexpr int THREADS = (BM / TM) * (BN / TN);
    __shared__ float As[BK][BM];
    __shared__ float Bs[BK][BN];

    const int tid  = threadIdx.x;
    const int row0 = blockIdx.y * BM;
    const int col0 = blockIdx.x * BN;
    constexpr int TCOLS = BN / TN;
    const int ty = tid / TCOLS;
    const int tx = tid % TCOLS;

    float acc[TM][TN];
    #pragma unroll
    for (int i = 0; i < TM; i++)
        #pragma unroll
        for (int j = 0; j < TN; j++) acc[i][j] = 0.f;

    for (int k0 = 0; k0 < K; k0 += BK) {
        // load A tile (float4 along K), store transposed As[k][m]
        #pragma unroll
        for (int i = 0; i < (BM * BK / 4) / THREADS; i++) {
            int idx = tid + i * THREADS;
            int r   = idx / (BK / 4);
            int kc  = (idx % (BK / 4)) * 4;
            float4 v = make_float4(0.f, 0.f, 0.f, 0.f);
            if (row0 + r < N)
                v = *(const float4*)(A + (size_t)(row0 + r) * K + k0 + kc);
            As[kc + 0][r] = v.x;
            As[kc + 1][r] = v.y;
            As[kc + 2][r] = v.z;
            As[kc + 3][r] = v.w;
        }
        // load B tile (float4 along N)
        #pragma unroll
        for (int i = 0; i < (BK * BN / 4) / THREADS; i++) {
            int idx = tid + i * THREADS;
            int r   = idx / (BN / 4);
            int nc  = (idx % (BN / 4)) * 4;
            *(float4*)(&Bs[r][nc]) =
                *(const float4*)(B + (size_t)(k0 + r) * M + col0 + nc);
        }
        __syncthreads();

        #pragma unroll
        for (int k = 0; k < BK; k++) {
            float ra[TM], rb[TN];
            #pragma unroll
            for (int i = 0; i < TM; i++) ra[i] = As[k][ty * TM + i];
            #pragma unroll
            for (int j = 0; j < TN; j++) rb[j] = Bs[k][tx * TN + j];
            #pragma unroll
            for (int i = 0; i < TM; i++)
                #pragma unroll
                for (int j = 0; j < TN; j++) acc[i][j] += ra[i] * rb[j];
        }
        __syncthreads();
    }

    #pragma unroll
    for (int i = 0; i < TM; i++) {
        int r = row0 + ty * TM + i;
        if (r < N) {
            #pragma unroll
            for (int j = 0; j < TN; j += 4) {
                *(float4*)(C + (size_t)r * M + col0 + tx * TN + j) =
                    make_float4(acc[i][j], acc[i][j + 1], acc[i][j + 2], acc[i][j + 3]);
            }
        }
    }
}

// ---- aggregation: out[i] = act(dinv[i]*(dinv[i]*xlin[i] + sum_r dinv[r]*xlin[r]) + b)
// xlin is always g_bufB; OUT_EXT selects external out vs. g_bufA scratch.
template <int C, bool SIG, bool OUT_EXT>
__global__ __launch_bounds__(C)
void k_agg(const float* __restrict__ bias, float* __restrict__ out_ext) {
    const float* __restrict__ xlin = g_bufB;
    float* __restrict__ out = OUT_EXT ? out_ext : (float*)g_bufA;

    const int i = blockIdx.x;
    const int c = threadIdx.x;
    const float di = g_dinv[i];
    float acc = di * xlin[(size_t)i * C + c];

    int p = g_off[i];
    const int e = g_off[i + 1];
    for (; p + 1 < e; p += 2) {
        int   r0 = g_csr[p],   r1 = g_csr[p + 1];
        float d0 = g_dinv[r0], d1 = g_dinv[r1];
        acc += d0 * xlin[(size_t)r0 * C + c];
        acc += d1 * xlin[(size_t)r1 * C + c];
    }
    if (p < e) {
        int r = g_csr[p];
        acc += g_dinv[r] * xlin[(size_t)r * C + c];
    }

    float v = di * acc + bias[c];
    if (SIG) v = 1.0f / (1.0f + __expf(-v));
    out[(size_t)i * C + c] = v;
}

// ---------------- launch: kernel launches ONLY, nothing else ----------------
extern "C" void kernel_launch(void* const* d_in, const int* in_sizes, int n_in,
                              void* d_out, int out_size) {
    const float* x   = (const float*)d_in[0];
    // d_in[1] = edge_attr (unused by forward)
    const void*  ei  = d_in[2];
    const float* W1  = (const float*)d_in[3];
    const float* b1  = (const float*)d_in[4];
    const float* W2  = (const float*)d_in[5];
    const float* b2  = (const float*)d_in[6];
    const float* W3  = (const float*)d_in[7];
    const float* b3  = (const float*)d_in[8];
    float*       out = (float*)d_out;

    const int n = NN;
    const int e = in_sizes[2] / 2;   // 800000 (element count / 2, dtype-agnostic)

    // ---- graph preprocessing (deterministic, recomputed every call)
    k_detect<<<1, 1>>>((const int*)ei);
    k_zero_deg<<<(n + 255) / 256, 256>>>(n);
    k_prep_edges<<<(e + 255) / 256, 256>>>(ei, e);
    k_dinv<<<(n + 255) / 256, 256>>>(n);
    k_scan<<<1, 1024>>>(n);
    k_fill_csr<<<(e + 255) / 256, 256>>>(e);

    // ---- layer 1: x[n,128] @ W1[128,256] -> bufB; agg+sigmoid -> bufA
    {
        dim3 grid(C_HID / 128, (n + 127) / 128);
        k_sgemm<128, 128, 16, 8, 8, true><<<grid, 256>>>(x, W1, n, C_IN, C_HID);
        k_agg<C_HID, true, false><<<n, C_HID>>>(b1, nullptr);
    }
    // ---- layer 2: bufA[n,256] @ W2[256,256] -> bufB; agg+sigmoid -> bufA
    {
        dim3 grid(C_HID / 128, (n + 127) / 128);
        k_sgemm<128, 128, 16, 8, 8, false><<<grid, 256>>>(nullptr, W2, n, C_HID, C_HID);
        k_agg<C_HID, true, false><<<n, C_HID>>>(b2, nullptr);
    }
    // ---- layer 3: bufA[n,256] @ W3[256,64] -> bufB; agg (no act) -> out
    {
        dim3 grid(C_OUT / 64, (n + 127) / 128);
        k_sgemm<128, 64, 16, 8, 4, false><<<grid, 256>>>(nullptr, W3, n, C_HID, C_OUT);
        k_agg<C_OUT, false, true><<<n, C_OUT>>>(b3, out);
    }
}

// round 8
// speedup vs baseline: 1.9342x; 1.9342x over previous
#include <cuda_runtime.h>
#include <cuda_bf16.h>
#include <math.h>
#include <stdint.h>

// Problem constants (fixed by the dataset)
#define NN    50000     // nodes
#define EE    800000    // edges
#define C_IN  128
#define C_HID 256
#define C_OUT 64

// ---------------- scratch (device globals; no allocation, no host API) -----
__device__ int   g_is64;            // 1 if edge_index delivered as int64
__device__ int   g_row[EE];
__device__ int   g_col[EE];
__device__ int   g_deg[NN];
__device__ float g_dinv[NN];
__device__ int   g_off[NN + 1];
__device__ int   g_cursor[NN];
__device__ int   g_csr[EE];
__device__ int   g_blksum[64];
__device__ float g_bufA[(size_t)NN * C_HID];
__device__ float g_bufB[(size_t)NN * C_HID];

// ---------------- dtype sniffer ---------------------------------------------
__global__ void k_detect(const int* __restrict__ ei32) {
    int all_zero = 1;
    #pragma unroll
    for (int i = 0; i < 64; i++)
        if (ei32[2 * i + 1] != 0) all_zero = 0;
    g_is64 = all_zero;
}

// ---------------- prep ------------------------------------------------------
__global__ void k_zero_deg(int n) {
    int i = blockIdx.x * blockDim.x + threadIdx.x;
    if (i < n) g_deg[i] = 0;
}

__global__ void k_prep_edges(const void* __restrict__ ei, int e) {
    int idx = blockIdx.x * blockDim.x + threadIdx.x;
    if (idx >= e) return;
    int r, c;
    if (g_is64) {
        const long long* p = (const long long*)ei;
        r = (int)p[idx];
        c = (int)p[(size_t)e + idx];
    } else {
        const int* p = (const int*)ei;
        r = p[idx];
        c = p[(size_t)e + idx];
    }
    g_row[idx] = r;
    g_col[idx] = c;
    atomicAdd(&g_deg[c], 1);
}

// block-level scan (1024 threads): local exclusive scan -> g_off, block sums
__global__ void k_scan1(int n) {
    __shared__ int wsum[32];
    int i = blockIdx.x * 1024 + threadIdx.x;
    int v = (i < n) ? g_deg[i] : 0;
    int lane = threadIdx.x & 31, w = threadIdx.x >> 5;
    int s = v;
    #pragma unroll
    for (int d = 1; d < 32; d <<= 1) {
        int t = __shfl_up_sync(~0u, s, d);
        if (lane >= d) s += t;
    }
    if (lane == 31) wsum[w] = s;
    __syncthreads();
    if (w == 0) {
        int ws = wsum[lane];
        #pragma unroll
        for (int d = 1; d < 32; d <<= 1) {
            int t = __shfl_up_sync(~0u, ws, d);
            if (lane >= d) ws += t;
        }
        wsum[lane] = ws;
    }
    __syncthreads();
    int excl = s - v + (w > 0 ? wsum[w - 1] : 0);
    if (i < n) g_off[i] = excl;
    if (threadIdx.x == 1023) g_blksum[blockIdx.x] = excl + v;
}

// scan the (<=64) block sums; write total to g_off[NN]
__global__ void k_scan2(int nb) {
    __shared__ int s[64];
    int t = threadIdx.x;
    int mine = (t < nb) ? g_blksum[t] : 0;
    s[t] = mine;
    __syncthreads();
    #pragma unroll
    for (int d = 1; d < 64; d <<= 1) {
        int v = (t >= d) ? s[t - d] : 0;
        __syncthreads();
        s[t] += v;
        __syncthreads();
    }
    g_blksum[t] = s[t] - mine;
    if (t == 63) g_off[NN] = s[63];
}

// add block offsets, init cursor, compute dinv (fused)
__global__ void k_scan3(int n) {
    int i = blockIdx.x * blockDim.x + threadIdx.x;
    if (i >= n) return;
    int off = g_off[i] + g_blksum[i >> 10];
    g_off[i] = off;
    g_cursor[i] = off;
    g_dinv[i] = rsqrtf((float)(g_deg[i] + 1));
}

__global__ void k_fill_csr(int e) {
    int idx = blockIdx.x * blockDim.x + threadIdx.x;
    if (idx >= e) return;
    int c = g_col[idx];
    int p = atomicAdd(&g_cursor[c], 1);
    g_csr[p] = g_row[idx];
}

// ---------------- tf32 helpers ----------------------------------------------
__device__ __forceinline__ uint32_t f2tf(float f) {
    uint32_t u;
    asm("cvt.rna.tf32.f32 %0, %1;" : "=r"(u) : "f"(f));
    return u;
}

__device__ __forceinline__ void mma_tf32(float c[4], const uint32_t a[4],
                                         const uint32_t b[2]) {
    asm volatile(
        "mma.sync.aligned.m16n8k8.row.col.f32.tf32.tf32.f32 "
        "{%0,%1,%2,%3}, {%4,%5,%6,%7}, {%8,%9}, {%0,%1,%2,%3};"
        : "+f"(c[0]), "+f"(c[1]), "+f"(c[2]), "+f"(c[3])
        : "r"(a[0]), "r"(a[1]), "r"(a[2]), "r"(a[3]), "r"(b[0]), "r"(b[1]));
}

// ---------------- tf32 GEMM: Out[N,M] = A[N,K] @ W[K,M] (+bias, +sigmoid) ----
// BM=128, BK=32, 256 threads (8 warps as 4x2), warp tile 32 x (BN/2).
template <int BN, bool SRC_B, bool DST_A, bool SIG, bool BIAS>
__global__ __launch_bounds__(256)
void k_gemm_tf32(const float* __restrict__ W, const float* __restrict__ bias,
                 int N, int K, int M) {
    const float* __restrict__ A = SRC_B ? (const float*)g_bufB : (const float*)g_bufA;
    float* __restrict__ Out = DST_A ? (float*)g_bufA : (float*)g_bufB;

    constexpr int WN = BN / 2;      // warp tile N
    constexpr int NT = WN / 8;      // n16n8 tiles per warp
    constexpr int NB = (BN * 32 / 4) / 256;  // float4 B loads per thread

    __shared__ __align__(16) float As[128][36];
    __shared__ __align__(16) float Bs[32][BN + 4];

    const int tid  = threadIdx.x;
    const int lane = tid & 31;
    const int warp = tid >> 5;
    const int wm   = warp >> 1;           // 0..3
    const int wn   = warp & 1;            // 0..1
    const int gi   = lane >> 2;           // 0..7
    const int ci   = lane & 3;            // 0..3
    const int row0 = blockIdx.y * 128;
    const int col0 = blockIdx.x * BN;

    float c[2][NT][4];
    #pragma unroll
    for (int mt = 0; mt < 2; mt++)
        #pragma unroll
        for (int nt = 0; nt < NT; nt++)
            #pragma unroll
            for (int j = 0; j < 4; j++) c[mt][nt][j] = 0.f;

    uint32_t aT[4][4];
    uint32_t bT[NB][4];

    const int KB = K / 32;

    // ---- stage loader: global -> regs (with tf32 rounding)
    auto load_stage = [&](int kb) {
        #pragma unroll
        for (int i = 0; i < 4; i++) {
            int idx = tid + i * 256;
            int r   = idx >> 3;
            int kc  = (idx & 7) * 4;
            float4 v = make_float4(0.f, 0.f, 0.f, 0.f);
            if (row0 + r < N)
                v = *(const float4*)(A + (size_t)(row0 + r) * K + kb * 32 + kc);
            aT[i][0] = f2tf(v.x); aT[i][1] = f2tf(v.y);
            aT[i][2] = f2tf(v.z); aT[i][3] = f2tf(v.w);
        }
        #pragma unroll
        for (int i = 0; i < NB; i++) {
            int idx = tid + i * 256;
            int r, nc;
            if (BN == 128) { r = idx >> 5; nc = (idx & 31) * 4; }
            else           { r = idx >> 4; nc = (idx & 15) * 4; }
            float4 v = *(const float4*)(W + (size_t)(kb * 32 + r) * M + col0 + nc);
            bT[i][0] = f2tf(v.x); bT[i][1] = f2tf(v.y);
            bT[i][2] = f2tf(v.z); bT[i][3] = f2tf(v.w);
        }
    };
    auto store_stage = [&]() {
        #pragma unroll
        for (int i = 0; i < 4; i++) {
            int idx = tid + i * 256;
            int r   = idx >> 3;
            int kc  = (idx & 7) * 4;
            *(uint4*)&As[r][kc] = *(uint4*)aT[i];
        }
        #pragma unroll
        for (int i = 0; i < NB; i++) {
            int idx = tid + i * 256;
            int r, nc;
            if (BN == 128) { r = idx >> 5; nc = (idx & 31) * 4; }
            else           { r = idx >> 4; nc = (idx & 15) * 4; }
            *(uint4*)&Bs[r][nc] = *(uint4*)bT[i];
        }
    };

    load_stage(0);
    store_stage();
    __syncthreads();

    for (int kb = 0; kb < KB; kb++) {
        if (kb + 1 < KB) load_stage(kb + 1);

        #pragma unroll
        for (int kk = 0; kk < 4; kk++) {
            const int k8 = kk * 8;
            uint32_t a[2][4];
            #pragma unroll
            for (int mt = 0; mt < 2; mt++) {
                int mr = wm * 32 + mt * 16 + gi;
                a[mt][0] = __float_as_uint(As[mr    ][k8     + ci]);
                a[mt][1] = __float_as_uint(As[mr + 8][k8     + ci]);
                a[mt][2] = __float_as_uint(As[mr    ][k8 + 4 + ci]);
                a[mt][3] = __float_as_uint(As[mr + 8][k8 + 4 + ci]);
            }
            uint32_t b[NT][2];
            #pragma unroll
            for (int nt = 0; nt < NT; nt++) {
                int nc = wn * WN + nt * 8 + gi;
                b[nt][0] = __float_as_uint(Bs[k8     + ci][nc]);
                b[nt][1] = __float_as_uint(Bs[k8 + 4 + ci][nc]);
            }
            #pragma unroll
            for (int mt = 0; mt < 2; mt++)
                #pragma unroll
                for (int nt = 0; nt < NT; nt++)
                    mma_tf32(c[mt][nt], a[mt], b[nt]);
        }

        if (kb + 1 < KB) {
            __syncthreads();
            store_stage();
            __syncthreads();
        }
    }

    // ---- epilogue: (+bias), (sigmoid), store float2 pairs
    #pragma unroll
    for (int mt = 0; mt < 2; mt++) {
        int r = row0 + wm * 32 + mt * 16 + gi;
        #pragma unroll
        for (int nt = 0; nt < NT; nt++) {
            int gcol = col0 + wn * WN + nt * 8 + ci * 2;
            float b0 = 0.f, b1 = 0.f;
            if (BIAS) { b0 = __ldg(bias + gcol); b1 = __ldg(bias + gcol + 1); }
            float v0 = c[mt][nt][0] + b0, v1 = c[mt][nt][1] + b1;
            float v2 = c[mt][nt][2] + b0, v3 = c[mt][nt][3] + b1;
            if (SIG) {
                v0 = 1.f / (1.f + __expf(-v0));
                v1 = 1.f / (1.f + __expf(-v1));
                v2 = 1.f / (1.f + __expf(-v2));
                v3 = 1.f / (1.f + __expf(-v3));
            }
            if (r < N)
                *(float2*)(Out + (size_t)r * M + gcol) = make_float2(v0, v1);
            if (r + 8 < N)
                *(float2*)(Out + (size_t)(r + 8) * M + gcol) = make_float2(v2, v3);
        }
    }
}

// ---------------- aggregation (float4 lanes, multiple nodes per block) -------
// out[i] = dinv[i] * ( sum_r dinv[r]*in[r] + dinv[i]*in[i] )  (+bias)
// SRCSEL: 0=g_bufA, 1=g_bufB, 2=external
template <int C, int SRCSEL, bool OUT_EXT, bool BIAS>
__global__ __launch_bounds__(128)
void k_agg(const float* __restrict__ in_ext, const float* __restrict__ bias,
           float* __restrict__ out_ext) {
    constexpr int T   = C / 4;       // threads per node
    constexpr int NPB = 128 / T;     // nodes per block
    const float* __restrict__ in =
        (SRCSEL == 2) ? in_ext
        : (SRCSEL == 0 ? (const float*)g_bufA : (const float*)g_bufB);
    float* __restrict__ out = OUT_EXT ? out_ext : (float*)g_bufA;

    const int node = blockIdx.x * NPB + threadIdx.x / T;
    if (node >= NN) return;
    const int c4 = (threadIdx.x % T) * 4;

    const float di = g_dinv[node];
    float4 s = __ldg((const float4*)(in + (size_t)node * C + c4));
    float ax = di * s.x, ay = di * s.y, az = di * s.z, aw = di * s.w;

    int p = g_off[node];
    const int e = g_off[node + 1];
    for (; p + 1 < e; p += 2) {
        int   r0 = g_csr[p],   r1 = g_csr[p + 1];
        float d0 = g_dinv[r0], d1 = g_dinv[r1];
        float4 v0 = __ldg((const float4*)(in + (size_t)r0 * C + c4));
        float4 v1 = __ldg((const float4*)(in + (size_t)r1 * C + c4));
        ax += d0 * v0.x + d1 * v1.x;
        ay += d0 * v0.y + d1 * v1.y;
        az += d0 * v0.z + d1 * v1.z;
        aw += d0 * v0.w + d1 * v1.w;
    }
    if (p < e) {
        int r = g_csr[p];
        float d = g_dinv[r];
        float4 v = __ldg((const float4*)(in + (size_t)r * C + c4));
        ax += d * v.x; ay += d * v.y; az += d * v.z; aw += d * v.w;
    }

    float4 o = make_float4(di * ax, di * ay, di * az, di * aw);
    if (BIAS) {
        float4 b = __ldg((const float4*)(bias + c4));
        o.x += b.x; o.y += b.y; o.z += b.z; o.w += b.w;
    }
    *(float4*)(out + (size_t)node * C + c4) = o;
}

// ---------------- launch: kernel launches ONLY -------------------------------
extern "C" void kernel_launch(void* const* d_in, const int* in_sizes, int n_in,
                              void* d_out, int out_size) {
    const float* x   = (const float*)d_in[0];
    // d_in[1] = edge_attr (unused by forward)
    const void*  ei  = d_in[2];
    const float* W1  = (const float*)d_in[3];
    const float* b1  = (const float*)d_in[4];
    const float* W2  = (const float*)d_in[5];
    const float* b2  = (const float*)d_in[6];
    const float* W3  = (const float*)d_in[7];
    const float* b3  = (const float*)d_in[8];
    float*       out = (float*)d_out;

    const int n = NN;
    const int e = in_sizes[2] / 2;             // 800000
    const int nblk = (n + 1023) / 1024;        // 49

    // ---- graph preprocessing
    k_detect<<<1, 1>>>((const int*)ei);
    k_zero_deg<<<(n + 255) / 256, 256>>>(n);
    k_prep_edges<<<(e + 255) / 256, 256>>>(ei, e);
    k_scan1<<<nblk, 1024>>>(n);
    k_scan2<<<1, 64>>>(nblk);
    k_scan3<<<(n + 255) / 256, 256>>>(n);
    k_fill_csr<<<(e + 255) / 256, 256>>>(e);

    // ---- layer 1: aggregate x (128ch) -> bufA; GEMM+bias+sigmoid -> bufB
    k_agg<C_IN, 2, false, false><<<NN / 4, 128>>>(x, nullptr, nullptr);
    {
        dim3 grid(C_HID / 128, (n + 127) / 128);
        k_gemm_tf32<128, false, false, true, true><<<grid, 256>>>(W1, b1, n, C_IN, C_HID);
    }
    // ---- layer 2: aggregate bufB (256ch) -> bufA; GEMM+bias+sigmoid -> bufB
    k_agg<C_HID, 1, false, false><<<NN / 2, 128>>>(nullptr, nullptr, nullptr);
    {
        dim3 grid(C_HID / 128, (n + 127) / 128);
        k_gemm_tf32<128, false, false, true, true><<<grid, 256>>>(W2, b2, n, C_HID, C_HID);
    }
    // ---- layer 3: GEMM bufB @ W3 -> bufA (64ch); aggregate + bias -> out
    {
        dim3 grid(C_OUT / 64, (n + 127) / 128);
        k_gemm_tf32<64, true, true, false, false><<<grid, 256>>>(W3, nullptr, n, C_HID, C_OUT);
    }
    k_agg<C_OUT, 0, true, true><<<NN / 8, 128>>>(nullptr, b3, out);
}

// round 9
// speedup vs baseline: 2.4413x; 1.2622x over previous
#include <cuda_runtime.h>
#include <cuda_bf16.h>
#include <math.h>
#include <stdint.h>

// Problem constants (fixed by the dataset)
#define NN    50000     // nodes
#define EE    800000    // edges
#define C_IN  128
#define C_HID 256
#define C_OUT 64

// ---------------- scratch (device globals; no allocation, no host API) -----
__device__ int   g_is64;            // 1 if edge_index delivered as int64
__device__ int   g_row[EE];
__device__ int   g_col[EE];
__device__ int   g_deg[NN];
__device__ float g_dinv[NN];
__device__ int   g_off[NN + 1];
__device__ int   g_cursor[NN];
__device__ int   g_csr[EE];
__device__ int   g_blksum[64];
__device__ float g_bufA[(size_t)NN * C_HID];
__device__ float g_bufB[(size_t)NN * C_HID];

// ---------------- prep ------------------------------------------------------
// zero degrees + (thread 0) sniff edge_index dtype: int64 node ids < 2^31 have
// every odd int32 word == 0; genuine int32 ids can't (P ~ (2e-5)^64).
__global__ void k_zero_deg(const int* __restrict__ ei32, int n) {
    int i = blockIdx.x * blockDim.x + threadIdx.x;
    if (i < n) g_deg[i] = 0;
    if (blockIdx.x == 0 && threadIdx.x == 0) {
        int all_zero = 1;
        #pragma unroll
        for (int k = 0; k < 64; k++)
            if (ei32[2 * k + 1] != 0) all_zero = 0;
        g_is64 = all_zero;
    }
}

__global__ void k_prep_edges(const void* __restrict__ ei, int e) {
    int idx = blockIdx.x * blockDim.x + threadIdx.x;
    if (idx >= e) return;
    int r, c;
    if (g_is64) {
        const long long* p = (const long long*)ei;
        r = (int)p[idx];
        c = (int)p[(size_t)e + idx];
    } else {
        const int* p = (const int*)ei;
        r = p[idx];
        c = p[(size_t)e + idx];
    }
    g_row[idx] = r;
    g_col[idx] = c;
    atomicAdd(&g_deg[c], 1);
}

// block-level scan (1024 threads): local exclusive scan -> g_off, block sums
__global__ void k_scan1(int n) {
    __shared__ int wsum[32];
    int i = blockIdx.x * 1024 + threadIdx.x;
    int v = (i < n) ? g_deg[i] : 0;
    int lane = threadIdx.x & 31, w = threadIdx.x >> 5;
    int s = v;
    #pragma unroll
    for (int d = 1; d < 32; d <<= 1) {
        int t = __shfl_up_sync(~0u, s, d);
        if (lane >= d) s += t;
    }
    if (lane == 31) wsum[w] = s;
    __syncthreads();
    if (w == 0) {
        int ws = wsum[lane];
        #pragma unroll
        for (int d = 1; d < 32; d <<= 1) {
            int t = __shfl_up_sync(~0u, ws, d);
            if (lane >= d) ws += t;
        }
        wsum[lane] = ws;
    }
    __syncthreads();
    int excl = s - v + (w > 0 ? wsum[w - 1] : 0);
    if (i < n) g_off[i] = excl;
    if (threadIdx.x == 1023) g_blksum[blockIdx.x] = excl + v;
}

__global__ void k_scan2(int nb) {
    __shared__ int s[64];
    int t = threadIdx.x;
    int mine = (t < nb) ? g_blksum[t] : 0;
    s[t] = mine;
    __syncthreads();
    #pragma unroll
    for (int d = 1; d < 64; d <<= 1) {
        int v = (t >= d) ? s[t - d] : 0;
        __syncthreads();
        s[t] += v;
        __syncthreads();
    }
    g_blksum[t] = s[t] - mine;
    if (t == 63) g_off[NN] = s[63];
}

__global__ void k_scan3(int n) {
    int i = blockIdx.x * blockDim.x + threadIdx.x;
    if (i >= n) return;
    int off = g_off[i] + g_blksum[i >> 10];
    g_off[i] = off;
    g_cursor[i] = off;
    g_dinv[i] = rsqrtf((float)(g_deg[i] + 1));
}

__global__ void k_fill_csr(int e) {
    int idx = blockIdx.x * blockDim.x + threadIdx.x;
    if (idx >= e) return;
    int c = g_col[idx];
    int p = atomicAdd(&g_cursor[c], 1);
    g_csr[p] = g_row[idx];
}

// ---------------- tf32 helpers ----------------------------------------------
__device__ __forceinline__ uint32_t f2tf(float f) {
    uint32_t u;
    asm("cvt.rna.tf32.f32 %0, %1;" : "=r"(u) : "f"(f));
    return u;
}

__device__ __forceinline__ void mma_tf32(float c[4], const uint32_t a[4],
                                         const uint32_t b[2]) {
    asm volatile(
        "mma.sync.aligned.m16n8k8.row.col.f32.tf32.tf32.f32 "
        "{%0,%1,%2,%3}, {%4,%5,%6,%7}, {%8,%9}, {%0,%1,%2,%3};"
        : "+f"(c[0]), "+f"(c[1]), "+f"(c[2]), "+f"(c[3])
        : "r"(a[0]), "r"(a[1]), "r"(a[2]), "r"(a[3]), "r"(b[0]), "r"(b[1]));
}

// ---------------- tf32 GEMM: Out[N,M] = A[N,K] @ W[K,M] (+bias, +sigmoid) ----
// BM=128, BK=16, double-buffered smem, 256 threads (8 warps as 4x2),
// warp tile 32 x (BN/2). Conflict-free smem strides: As 20, Bs BN+8.
template <int BN, bool SRC_B, bool DST_A, bool SIG, bool BIAS>
__global__ __launch_bounds__(256)
void k_gemm_tf32(const float* __restrict__ W, const float* __restrict__ bias,
                 int N, int K, int M) {
    const float* __restrict__ A = SRC_B ? (const float*)g_bufB : (const float*)g_bufA;
    float* __restrict__ Out = DST_A ? (float*)g_bufA : (float*)g_bufB;

    constexpr int WN   = BN / 2;             // warp tile N
    constexpr int NT   = WN / 8;             // m16n8 tiles per warp
    constexpr int NBLD = (BN == 128) ? 2 : 1;  // B float4 loads per thread/stage

    __shared__ __align__(16) float As[2][128][20];     // stride 20: banks gi*4+ci unique
    __shared__ __align__(16) float Bs[2][16][BN + 8];  // stride mod 32 = 8: ci*8+gi unique

    const int tid  = threadIdx.x;
    const int lane = tid & 31;
    const int warp = tid >> 5;
    const int wm   = warp >> 1;           // 0..3
    const int wn   = warp & 1;            // 0..1
    const int gi   = lane >> 2;           // 0..7
    const int ci   = lane & 3;            // 0..3
    const int row0 = blockIdx.y * 128;
    const int col0 = blockIdx.x * BN;

    float c[2][NT][4];
    #pragma unroll
    for (int mt = 0; mt < 2; mt++)
        #pragma unroll
        for (int nt = 0; nt < NT; nt++)
            #pragma unroll
            for (int j = 0; j < 4; j++) c[mt][nt][j] = 0.f;

    uint32_t aT[2][4];
    uint32_t bT[NBLD][4];
    const int KB = K / 16;

    auto load_regs = [&](int kb) {
        #pragma unroll
        for (int i = 0; i < 2; i++) {
            int idx = tid + i * 256;
            int r   = idx >> 2;            // 4 float4 chunks per 16-wide row
            int kc  = (idx & 3) * 4;
            float4 v = make_float4(0.f, 0.f, 0.f, 0.f);
            if (row0 + r < N)
                v = *(const float4*)(A + (size_t)(row0 + r) * K + kb * 16 + kc);
            aT[i][0] = f2tf(v.x); aT[i][1] = f2tf(v.y);
            aT[i][2] = f2tf(v.z); aT[i][3] = f2tf(v.w);
        }
        #pragma unroll
        for (int i = 0; i < NBLD; i++) {
            int idx = tid + i * 256;
            int r, nc;
            if (BN == 128) { r = idx >> 5; nc = (idx & 31) * 4; }
            else           { r = idx >> 4; nc = (idx & 15) * 4; }
            float4 v = *(const float4*)(W + (size_t)(kb * 16 + r) * M + col0 + nc);
            bT[i][0] = f2tf(v.x); bT[i][1] = f2tf(v.y);
            bT[i][2] = f2tf(v.z); bT[i][3] = f2tf(v.w);
        }
    };
    auto store_regs = [&](int s) {
        #pragma unroll
        for (int i = 0; i < 2; i++) {
            int idx = tid + i * 256;
            int r   = idx >> 2;
            int kc  = (idx & 3) * 4;
            *(uint4*)&As[s][r][kc] = *(uint4*)aT[i];
        }
        #pragma unroll
        for (int i = 0; i < NBLD; i++) {
            int idx = tid + i * 256;
            int r, nc;
            if (BN == 128) { r = idx >> 5; nc = (idx & 31) * 4; }
            else           { r = idx >> 4; nc = (idx & 15) * 4; }
            *(uint4*)&Bs[s][r][nc] = *(uint4*)bT[i];
        }
    };

    load_regs(0);
    store_regs(0);
    __syncthreads();

    for (int kb = 0; kb < KB; kb++) {
        if (kb + 1 < KB) load_regs(kb + 1);   // LDG in flight over the mma burst
        const int s = kb & 1;

        #pragma unroll
        for (int kk = 0; kk < 2; kk++) {
            const int k8 = kk * 8;
            uint32_t a[2][4];
            #pragma unroll
            for (int mt = 0; mt < 2; mt++) {
                int mr = wm * 32 + mt * 16 + gi;
                a[mt][0] = __float_as_uint(As[s][mr    ][k8     + ci]);
                a[mt][1] = __float_as_uint(As[s][mr + 8][k8     + ci]);
                a[mt][2] = __float_as_uint(As[s][mr    ][k8 + 4 + ci]);
                a[mt][3] = __float_as_uint(As[s][mr + 8][k8 + 4 + ci]);
            }
            uint32_t b[NT][2];
            #pragma unroll
            for (int nt = 0; nt < NT; nt++) {
                int nc = wn * WN + nt * 8 + gi;
                b[nt][0] = __float_as_uint(Bs[s][k8     + ci][nc]);
                b[nt][1] = __float_as_uint(Bs[s][k8 + 4 + ci][nc]);
            }
            #pragma unroll
            for (int mt = 0; mt < 2; mt++)
                #pragma unroll
                for (int nt = 0; nt < NT; nt++)
                    mma_tf32(c[mt][nt], a[mt], b[nt]);
        }

        if (kb + 1 < KB) {
            store_regs((kb + 1) & 1);   // other buffer; prior sync guarantees readers done
            __syncthreads();
        }
    }

    // ---- epilogue: (+bias), (sigmoid), store float2 pairs
    #pragma unroll
    for (int mt = 0; mt < 2; mt++) {
        int r = row0 + wm * 32 + mt * 16 + gi;
        #pragma unroll
        for (int nt = 0; nt < NT; nt++) {
            int gcol = col0 + wn * WN + nt * 8 + ci * 2;
            float b0 = 0.f, b1 = 0.f;
            if (BIAS) { b0 = __ldg(bias + gcol); b1 = __ldg(bias + gcol + 1); }
            float v0 = c[mt][nt][0] + b0, v1 = c[mt][nt][1] + b1;
            float v2 = c[mt][nt][2] + b0, v3 = c[mt][nt][3] + b1;
            if (SIG) {
                v0 = 1.f / (1.f + __expf(-v0));
                v1 = 1.f / (1.f + __expf(-v1));
                v2 = 1.f / (1.f + __expf(-v2));
                v3 = 1.f / (1.f + __expf(-v3));
            }
            if (r < N)
                *(float2*)(Out + (size_t)r * M + gcol) = make_float2(v0, v1);
            if (r + 8 < N)
                *(float2*)(Out + (size_t)(r + 8) * M + gcol) = make_float2(v2, v3);
        }
    }
}

// ---------------- aggregation (float4 lanes, multiple nodes per block) -------
// out[i] = dinv[i] * ( sum_r dinv[r]*in[r] + dinv[i]*in[i] )  (+bias)
// SRCSEL: 0=g_bufA, 1=g_bufB, 2=external
template <int C, int SRCSEL, bool OUT_EXT, bool BIAS>
__global__ __launch_bounds__(128)
void k_agg(const float* __restrict__ in_ext, const float* __restrict__ bias,
           float* __restrict__ out_ext) {
    constexpr int T   = C / 4;       // threads per node
    constexpr int NPB = 128 / T;     // nodes per block
    const float* __restrict__ in =
        (SRCSEL == 2) ? in_ext
        : (SRCSEL == 0 ? (const float*)g_bufA : (const float*)g_bufB);
    float* __restrict__ out = OUT_EXT ? out_ext : (float*)g_bufA;

    const int node = blockIdx.x * NPB + threadIdx.x / T;
    if (node >= NN) return;
    const int c4 = (threadIdx.x % T) * 4;

    const float di = g_dinv[node];
    float4 s = __ldg((const float4*)(in + (size_t)node * C + c4));
    float ax = di * s.x, ay = di * s.y, az = di * s.z, aw = di * s.w;

    int p = g_off[node];
    const int e = g_off[node + 1];
    for (; p + 1 < e; p += 2) {
        int   r0 = g_csr[p],   r1 = g_csr[p + 1];
        float d0 = g_dinv[r0], d1 = g_dinv[r1];
        float4 v0 = __ldg((const float4*)(in + (size_t)r0 * C + c4));
        float4 v1 = __ldg((const float4*)(in + (size_t)r1 * C + c4));
        ax += d0 * v0.x + d1 * v1.x;
        ay += d0 * v0.y + d1 * v1.y;
        az += d0 * v0.z + d1 * v1.z;
        aw += d0 * v0.w + d1 * v1.w;
    }
    if (p < e) {
        int r = g_csr[p];
        float d = g_dinv[r];
        float4 v = __ldg((const float4*)(in + (size_t)r * C + c4));
        ax += d * v.x; ay += d * v.y; az += d * v.z; aw += d * v.w;
    }

    float4 o = make_float4(di * ax, di * ay, di * az, di * aw);
    if (BIAS) {
        float4 b = __ldg((const float4*)(bias + c4));
        o.x += b.x; o.y += b.y; o.z += b.z; o.w += b.w;
    }
    *(float4*)(out + (size_t)node * C + c4) = o;
}

// ---------------- launch: kernel launches ONLY -------------------------------
extern "C" void kernel_launch(void* const* d_in, const int* in_sizes, int n_in,
                              void* d_out, int out_size) {
    const float* x   = (const float*)d_in[0];
    // d_in[1] = edge_attr (unused by forward)
    const void*  ei  = d_in[2];
    const float* W1  = (const float*)d_in[3];
    const float* b1  = (const float*)d_in[4];
    const float* W2  = (const float*)d_in[5];
    const float* b2  = (const float*)d_in[6];
    const float* W3  = (const float*)d_in[7];
    const float* b3  = (const float*)d_in[8];
    float*       out = (float*)d_out;

    const int n = NN;
    const int e = in_sizes[2] / 2;             // 800000
    const int nblk = (n + 1023) / 1024;        // 49

    // ---- graph preprocessing
    k_zero_deg<<<(n + 255) / 256, 256>>>((const int*)ei, n);
    k_prep_edges<<<(e + 255) / 256, 256>>>(ei, e);
    k_scan1<<<nblk, 1024>>>(n);
    k_scan2<<<1, 64>>>(nblk);
    k_scan3<<<(n + 255) / 256, 256>>>(n);
    k_fill_csr<<<(e + 255) / 256, 256>>>(e);

    // ---- layer 1: aggregate x (128ch) -> bufA; GEMM+bias+sigmoid -> bufB
    k_agg<C_IN, 2, false, false><<<NN / 4, 128>>>(x, nullptr, nullptr);
    {
        dim3 grid(C_HID / 128, (n + 127) / 128);
        k_gemm_tf32<128, false, false, true, true><<<grid, 256>>>(W1, b1, n, C_IN, C_HID);
    }
    // ---- layer 2: aggregate bufB (256ch) -> bufA; GEMM+bias+sigmoid -> bufB
    k_agg<C_HID, 1, false, false><<<NN / 2, 128>>>(nullptr, nullptr, nullptr);
    {
        dim3 grid(C_HID / 128, (n + 127) / 128);
        k_gemm_tf32<128, false, false, true, true><<<grid, 256>>>(W2, b2, n, C_HID, C_HID);
    }
    // ---- layer 3: GEMM bufB @ W3 -> bufA (64ch); aggregate + bias -> out
    {
        dim3 grid(C_OUT / 64, (n + 127) / 128);
        k_gemm_tf32<64, true, true, false, false><<<grid, 256>>>(W3, nullptr, n, C_HID, C_OUT);
    }
    k_agg<C_OUT, 0, true, true><<<NN / 8, 128>>>(nullptr, b3, out);
}